// round 12
// baseline (speedup 1.0000x reference)
#include <cuda_runtime.h>
#include <cuda_fp16.h>
#include <math.h>
#include <stdint.h>

#define NB 2
#define NS 2048
#define NE 128
#define NH 16
#define ND 128
#define NINNER 2048
#define NROWS 4096
#define HALF 64

// Scratch
__device__ __half g_Qh[NB*NH*NS*ND];
__device__ __half g_Kh[NB*NH*NS*ND];
__device__ __half g_Vh[NB*NH*NS*ND];
__device__ __half g_Oh[NB*NH*NS*ND];
__device__ __half g_Woh[NINNER*NE];
__device__ __half g_Wqh[NE*NINNER];
__device__ __half g_Wkh[NE*NINNER];
__device__ __half g_Wvh[NE*NINNER];
__device__ __half g_qhi[NROWS*NE];
__device__ __half g_qlo[NROWS*NE];
__device__ float2 g_rope[NS*HALF];

// ---------------------------------------------------------------------------
__global__ void rope_table_kernel() {
    int idx = blockIdx.x * 256 + threadIdx.x;
    if (idx >= NS * HALF) return;
    int s = idx / HALF, p = idx % HALF;
    double inv = exp(-(double)p * (log(10000.0) / 64.0));
    double a = (double)s * inv;
    g_rope[idx] = make_float2((float)cos(a), (float)sin(a));
}

// ---------------------------------------------------------------------------
// helpers
// ---------------------------------------------------------------------------
__device__ __forceinline__ void mma16(float* c, uint32_t a0, uint32_t a1,
                                      uint32_t a2, uint32_t a3,
                                      uint32_t b0, uint32_t b1) {
    asm("mma.sync.aligned.m16n8k16.row.col.f32.f16.f16.f32 "
        "{%0,%1,%2,%3},{%4,%5,%6,%7},{%8,%9},{%0,%1,%2,%3};"
        : "+f"(c[0]), "+f"(c[1]), "+f"(c[2]), "+f"(c[3])
        : "r"(a0), "r"(a1), "r"(a2), "r"(a3), "r"(b0), "r"(b1));
}
__device__ __forceinline__ void ldsm_x4(uint32_t* r, uint32_t addr) {
    asm volatile("ldmatrix.sync.aligned.m8n8.x4.shared.b16 {%0,%1,%2,%3}, [%4];"
        : "=r"(r[0]), "=r"(r[1]), "=r"(r[2]), "=r"(r[3]) : "r"(addr));
}
__device__ __forceinline__ void ldsm_x4t(uint32_t* r, uint32_t addr) {
    asm volatile("ldmatrix.sync.aligned.m8n8.x4.trans.shared.b16 {%0,%1,%2,%3}, [%4];"
        : "=r"(r[0]), "=r"(r[1]), "=r"(r[2]), "=r"(r[3]) : "r"(addr));
}
__device__ __forceinline__ float ex2(float x) {
    float y;
    asm("ex2.approx.f32 %0, %1;" : "=f"(y) : "f"(x));
    return y;
}
__device__ __forceinline__ uint32_t h2ex2(uint32_t x) {
    uint32_t y;
    asm("ex2.approx.f16x2 %0, %1;" : "=r"(y) : "r"(x));
    return y;
}
__device__ __forceinline__ uint32_t pack2(float a, float b) {
    __half2 h = __floats2half2_rn(a, b);
    return *(uint32_t*)&h;
}
__device__ __forceinline__ void cp16(uint32_t dst, const void* src) {
    asm volatile("cp.async.cg.shared.global [%0], [%1], 16;"
                 :: "r"(dst), "l"(src));
}
__device__ __forceinline__ void cp_commit() {
    asm volatile("cp.async.commit_group;");
}
template <int N>
__device__ __forceinline__ void cp_wait() {
    asm volatile("cp.async.wait_group %0;" :: "n"(N));
}

// ---------------------------------------------------------------------------
// Kernel 0b: convert weight matrices to half
// ---------------------------------------------------------------------------
__global__ void wconv_kernel(const float* __restrict__ Wq, const float* __restrict__ Wk,
                             const float* __restrict__ Wv, const float* __restrict__ Wo) {
    int z = blockIdx.z;
    const float* src = (z == 0) ? Wq : (z == 1) ? Wk : (z == 2) ? Wv : Wo;
    __half* dst = (z == 0) ? g_Wqh : (z == 1) ? g_Wkh : (z == 2) ? g_Wvh : g_Woh;
    int i = blockIdx.x * 256 + threadIdx.x;
    float4 v = *(const float4*)&src[(size_t)i * 4];
    *(uint2*)&dst[(size_t)i * 4] = make_uint2(pack2(v.x, v.y), pack2(v.z, v.w));
}

// ---------------------------------------------------------------------------
// Kernel 0c: split activations q into f16 hi + f16 residual lo
// ---------------------------------------------------------------------------
__global__ void qsplit_kernel(const float* __restrict__ q) {
    int i = blockIdx.x * 256 + threadIdx.x;
    float4 v = *(const float4*)&q[(size_t)i * 4];
    __half hx = __float2half_rn(v.x), hy = __float2half_rn(v.y);
    __half hz = __float2half_rn(v.z), hw = __float2half_rn(v.w);
    __half2 h0 = __halves2half2(hx, hy), h1 = __halves2half2(hz, hw);
    *(uint2*)&g_qhi[(size_t)i * 4] = make_uint2(*(uint32_t*)&h0, *(uint32_t*)&h1);
    float lx = v.x - __half2float(hx), ly = v.y - __half2float(hy);
    float lz = v.z - __half2float(hz), lw = v.w - __half2float(hw);
    *(uint2*)&g_qlo[(size_t)i * 4] = make_uint2(pack2(lx, ly), pack2(lz, lw));
}

// ---------------------------------------------------------------------------
// Kernel 1: fused QKV projection, fp16 mma with split-A compensation + RoPE.
// ---------------------------------------------------------------------------
#define PPITCH 272
#define PA_SZ (128 * PPITCH)
#define PROJ_SMEM (3 * PA_SZ)

__global__ __launch_bounds__(256, 1) void proj_kernel() {
    extern __shared__ char psm[];
    uint32_t sbase = (uint32_t)__cvta_generic_to_shared(psm);
    uint32_t ahi_off = 0, alo_off = PA_SZ, b_off = 2 * PA_SZ;

    int z = blockIdx.z;
    const __half* W = (z == 0) ? g_Wqh : (z == 1) ? g_Wkh : g_Wvh;
    __half* dst = (z == 0) ? g_Qh : (z == 1) ? g_Kh : g_Vh;

    int h = blockIdx.x;
    int row0 = blockIdx.y * 128;
    int col0 = h * 128;
    int tid = threadIdx.x;
    int wid = tid >> 5, lane = tid & 31;
    int lg = lane >> 2, lc = lane & 3;

    #pragma unroll
    for (int j = 0; j < 8; j++) {
        int idx = tid + j * 256;
        int r = idx >> 4, c = (idx & 15) << 4;
        cp16(sbase + ahi_off + r * PPITCH + c,
             (const char*)&g_qhi[(size_t)(row0 + r) * NE] + c);
        cp16(sbase + alo_off + r * PPITCH + c,
             (const char*)&g_qlo[(size_t)(row0 + r) * NE] + c);
        cp16(sbase + b_off + r * PPITCH + c,
             (const char*)&W[(size_t)r * NINNER + col0] + c);
    }
    cp_commit();
    cp_wait<0>();
    __syncthreads();

    uint32_t laneQ = ((lane & 7) + ((lane >> 3) & 1) * 8) * PPITCH + ((lane >> 4) & 1) * 16;

    uint32_t ahi[8][4], alo[8][4];
    {
        uint32_t abase_h = sbase + ahi_off + wid * 16 * PPITCH + laneQ;
        uint32_t abase_l = sbase + alo_off + wid * 16 * PPITCH + laneQ;
        #pragma unroll
        for (int kg = 0; kg < 8; kg++) {
            ldsm_x4(ahi[kg], abase_h + kg * 32);
            ldsm_x4(alo[kg], abase_l + kg * 32);
        }
    }

    float acc[16][4] = {};
    uint32_t bbase = sbase + b_off + laneQ;
    #pragma unroll
    for (int kg = 0; kg < 8; kg++) {
        #pragma unroll
        for (int nbp = 0; nbp < 8; nbp++) {
            uint32_t br[4];
            ldsm_x4t(br, bbase + kg * (16 * PPITCH) + nbp * 32);
            mma16(acc[2 * nbp],     ahi[kg][0], ahi[kg][1], ahi[kg][2], ahi[kg][3], br[0], br[1]);
            mma16(acc[2 * nbp],     alo[kg][0], alo[kg][1], alo[kg][2], alo[kg][3], br[0], br[1]);
            mma16(acc[2 * nbp + 1], ahi[kg][0], ahi[kg][1], ahi[kg][2], ahi[kg][3], br[2], br[3]);
            mma16(acc[2 * nbp + 1], alo[kg][0], alo[kg][1], alo[kg][2], alo[kg][3], br[2], br[3]);
        }
    }

    const float qscale = 0.08838834764831845f * 1.4426950408889634f;
    float oscale = (z == 0) ? qscale : 1.0f;
    bool do_rope = (z < 2);

    int row_a = row0 + wid * 16 + lg;
    int b = row_a >> 11;
    int s0 = row_a & (NS - 1);
    int s1 = s0 + 8;
    __half* d0p = &dst[((size_t)(b * NH + h) * NS + s0) * ND];
    __half* d1p = &dst[((size_t)(b * NH + h) * NS + s1) * ND];

    #pragma unroll
    for (int nb = 0; nb < 16; nb++) {
        int dcol = nb * 8 + 2 * lc;
        int p = nb * 4 + lc;
        float c0 = acc[nb][0], c1 = acc[nb][1];
        float c2 = acc[nb][2], c3 = acc[nb][3];
        if (do_rope) {
            float2 csa = g_rope[s0 * HALF + p];
            float2 csb = g_rope[s1 * HALF + p];
            float r0 = c0 * csa.x - c1 * csa.y;
            float r1 = c1 * csa.x + c0 * csa.y;
            float r2 = c2 * csb.x - c3 * csb.y;
            float r3 = c3 * csb.x + c2 * csb.y;
            c0 = r0; c1 = r1; c2 = r2; c3 = r3;
        }
        *(uint32_t*)&d0p[dcol] = pack2(c0 * oscale, c1 * oscale);
        *(uint32_t*)&d1p[dcol] = pack2(c2 * oscale, c3 * oscale);
    }
}

// ---------------------------------------------------------------------------
// Kernel 2: causal flash attention, fp16 mma, cp.async pipeline, DEFERRED PV.
// At iter kt: S-mma(kt) issued, then PV-mma(kt-1) (independent of softmax(kt))
// fills the tensor pipe while softmax(kt) waits on S results / MUFU.
// V triple-buffered; 3rd buffer overlays the dead Q staging region.
// ---------------------------------------------------------------------------
#define PITCHB 272
#define KS_SZ  (64 * PITCHB)
#define KS_OFF 0
#define VS_OFF (2 * KS_SZ)
#define QST_OFF (4 * KS_SZ)
#define ATTN_SMEM (QST_OFF + 128 * PITCHB)

__global__ __launch_bounds__(256, 1) void attn_kernel() {
    extern __shared__ char smem[];
    uint32_t sbase = (uint32_t)__cvta_generic_to_shared(smem);

    int qt = gridDim.x - 1 - blockIdx.x;   // heavy tiles first
    int h = blockIdx.y, b = blockIdx.z;
    const __half* Qg = &g_Qh[((size_t)(b * NH + h) * NS + qt * 128) * ND];
    const __half* Kg = &g_Kh[(size_t)(b * NH + h) * NS * ND];
    const __half* Vg = &g_Vh[(size_t)(b * NH + h) * NS * ND];

    int tid = threadIdx.x;
    int wid = tid >> 5, lane = tid & 31;
    int lg = lane >> 2, lc = lane & 3;

    int nkt = 2 * qt + 2;
    uint32_t ones_b = (lg == 0) ? 0x3C003C00u : 0u;

    // V buffer i lives at: i%3 in {VS_OFF, VS_OFF+KS_SZ, QST_OFF}
    auto voff = [&](int i) -> uint32_t {
        int m = i % 3;
        return (m < 2) ? (VS_OFF + m * KS_SZ) : QST_OFF;
    };

    // prologue: commit K0,V0; stage Q; load Q fragments
    {
        const char* sk = (const char*)Kg;
        const char* sv = (const char*)Vg;
        #pragma unroll
        for (int j = 0; j < 4; j++) {
            int idx = tid + j * 256;
            int r = idx >> 4, c = (idx & 15) << 4;
            cp16(sbase + KS_OFF + r * PITCHB + c, sk + r * 256 + c);
            cp16(sbase + VS_OFF + r * PITCHB + c, sv + r * 256 + c);
        }
        cp_commit();
    }
    #pragma unroll
    for (int j = 0; j < 8; j++) {
        int idx = tid + j * 256;
        int r = idx >> 4, c = (idx & 15) << 4;
        *(uint4*)(smem + QST_OFF + r * PITCHB + c) =
            *(const uint4*)((const char*)Qg + r * 256 + c);
    }
    __syncthreads();

    uint32_t laneQ = ((lane & 7) + ((lane >> 3) & 1) * 8) * PITCHB + ((lane >> 4) & 1) * 16;
    uint32_t laneK = ((lane & 7) + ((lane >> 4) & 1) * 8) * PITCHB + ((lane >> 3) & 1) * 16;
    uint32_t laneV = laneQ;

    uint32_t qa[8][4];
    {
        uint32_t qaddr = sbase + QST_OFF + wid * 16 * PITCHB + laneQ;
        #pragma unroll
        for (int kg = 0; kg < 8; kg++) ldsm_x4(qa[kg], qaddr + kg * 32);
    }
    __syncthreads();   // Q fragments read before V buf 2 may overwrite QST

    float oacc[16][4] = {};
    float lrow[4] = {};
    float m0 = -1e30f, m1 = -1e30f;
    int row_g0 = qt * 128 + wid * 16 + lg;
    int row_g1 = row_g0 + 8;

    uint32_t php[8][2];   // P fragments of previous tile

    for (int kt = 0; kt < nkt; kt++) {
        cp_wait<0>();
        __syncthreads();

        if (kt + 1 < nkt) {
            const char* sk = (const char*)(Kg + (size_t)(kt + 1) * 64 * ND);
            const char* sv = (const char*)(Vg + (size_t)(kt + 1) * 64 * ND);
            uint32_t kd = sbase + KS_OFF + ((kt + 1) & 1) * KS_SZ;
            uint32_t vd = sbase + voff(kt + 1);
            #pragma unroll
            for (int j = 0; j < 4; j++) {
                int idx = tid + j * 256;
                int r = idx >> 4, c = (idx & 15) << 4;
                cp16(kd + r * PITCHB + c, sk + r * 256 + c);
                cp16(vd + r * PITCHB + c, sv + r * 256 + c);
            }
            cp_commit();
        }

        // ---- S = Q @ K^T (kt) ----
        uint32_t kbase = sbase + KS_OFF + (kt & 1) * KS_SZ + laneK;
        float sacc[8][4] = {};
        #pragma unroll
        for (int kg = 0; kg < 8; kg++) {
            #pragma unroll
            for (int nbp = 0; nbp < 4; nbp++) {
                uint32_t br[4];
                ldsm_x4(br, kbase + nbp * (16 * PITCHB) + kg * 32);
                mma16(sacc[2 * nbp],     qa[kg][0], qa[kg][1], qa[kg][2], qa[kg][3], br[0], br[1]);
                mma16(sacc[2 * nbp + 1], qa[kg][0], qa[kg][1], qa[kg][2], qa[kg][3], br[2], br[3]);
            }
        }

        // ---- deferred PV: O += P(kt-1) @ V(kt-1) ----
        if (kt > 0) {
            uint32_t vbase = sbase + voff(kt - 1) + laneV;
            #pragma unroll
            for (int kg = 0; kg < 4; kg++) {
                uint32_t a0 = php[2 * kg][0], a1 = php[2 * kg][1];
                uint32_t a2 = php[2 * kg + 1][0], a3 = php[2 * kg + 1][1];
                #pragma unroll
                for (int nbp = 0; nbp < 8; nbp++) {
                    uint32_t br[4];
                    ldsm_x4t(br, vbase + kg * (16 * PITCHB) + nbp * 32);
                    mma16(oacc[2 * nbp],     a0, a1, a2, a3, br[0], br[1]);
                    mma16(oacc[2 * nbp + 1], a0, a1, a2, a3, br[2], br[3]);
                }
            }
        }

        // ---- causal mask ----
        if (kt >= 2 * qt) {
            #pragma unroll
            for (int nb = 0; nb < 8; nb++) {
                int col_g = kt * 64 + nb * 8 + 2 * lc;
                if (col_g     > row_g0) sacc[nb][0] = -1e30f;
                if (col_g + 1 > row_g0) sacc[nb][1] = -1e30f;
                if (col_g     > row_g1) sacc[nb][2] = -1e30f;
                if (col_g + 1 > row_g1) sacc[nb][3] = -1e30f;
            }
        }

        // ---- online softmax (log2 domain) ----
        float mt0 = -1e30f, mt1 = -1e30f;
        #pragma unroll
        for (int nb = 0; nb < 8; nb++) {
            mt0 = fmaxf(mt0, fmaxf(sacc[nb][0], sacc[nb][1]));
            mt1 = fmaxf(mt1, fmaxf(sacc[nb][2], sacc[nb][3]));
        }
        mt0 = fmaxf(mt0, __shfl_xor_sync(0xFFFFFFFFu, mt0, 1));
        mt0 = fmaxf(mt0, __shfl_xor_sync(0xFFFFFFFFu, mt0, 2));
        mt1 = fmaxf(mt1, __shfl_xor_sync(0xFFFFFFFFu, mt1, 1));
        mt1 = fmaxf(mt1, __shfl_xor_sync(0xFFFFFFFFu, mt1, 2));
        float mn0 = fmaxf(m0, mt0), mn1 = fmaxf(m1, mt1);
        float al0 = ex2(m0 - mn0), al1 = ex2(m1 - mn1);
        m0 = mn0; m1 = mn1;

        // rescale O (now includes PV up through kt-1) and l
        #pragma unroll
        for (int nb = 0; nb < 16; nb++) {
            oacc[nb][0] *= al0; oacc[nb][1] *= al0;
            oacc[nb][2] *= al1; oacc[nb][3] *= al1;
        }
        lrow[0] *= al0; lrow[1] *= al0; lrow[2] *= al1; lrow[3] *= al1;

        // p = 2^(s-m) in f16x2
        #pragma unroll
        for (int nb = 0; nb < 8; nb++) {
            php[nb][0] = h2ex2(pack2(sacc[nb][0] - mn0, sacc[nb][1] - mn0));
            php[nb][1] = h2ex2(pack2(sacc[nb][2] - mn1, sacc[nb][3] - mn1));
        }

        // l += P @ ones
        #pragma unroll
        for (int kg = 0; kg < 4; kg++)
            mma16(lrow, php[2 * kg][0], php[2 * kg][1],
                  php[2 * kg + 1][0], php[2 * kg + 1][1], ones_b, ones_b);
    }

    // ---- drain: final PV on last tile ----
    {
        uint32_t vbase = sbase + voff(nkt - 1) + laneV;
        #pragma unroll
        for (int kg = 0; kg < 4; kg++) {
            uint32_t a0 = php[2 * kg][0], a1 = php[2 * kg][1];
            uint32_t a2 = php[2 * kg + 1][0], a3 = php[2 * kg + 1][1];
            #pragma unroll
            for (int nbp = 0; nbp < 8; nbp++) {
                uint32_t br[4];
                ldsm_x4t(br, vbase + kg * (16 * PITCHB) + nbp * 32);
                mma16(oacc[2 * nbp],     a0, a1, a2, a3, br[0], br[1]);
                mma16(oacc[2 * nbp + 1], a0, a1, a2, a3, br[2], br[3]);
            }
        }
    }

    // ---- epilogue ----
    float lt0 = __shfl_sync(0xFFFFFFFFu, lrow[0], lane & 28);
    float lt1 = __shfl_sync(0xFFFFFFFFu, lrow[2], lane & 28);
    float inv0 = 1.0f / lt0, inv1 = 1.0f / lt1;
    __half* Og = &g_Oh[((size_t)(b * NH + h) * NS + qt * 128) * ND];
    #pragma unroll
    for (int nb = 0; nb < 16; nb++) {
        int c = nb * 8 + 2 * lc;
        *(uint32_t*)&Og[(size_t)(wid * 16 + lg) * ND + c] =
            pack2(oacc[nb][0] * inv0, oacc[nb][1] * inv0);
        *(uint32_t*)&Og[(size_t)(wid * 16 + lg + 8) * ND + c] =
            pack2(oacc[nb][2] * inv1, oacc[nb][3] * inv1);
    }
}

// ---------------------------------------------------------------------------
__global__ void zero_kernel(float* __restrict__ out, int n) {
    int i = blockIdx.x * 256 + threadIdx.x;
    if (i * 4 < n) *(float4*)&out[i * 4] = make_float4(0.f, 0.f, 0.f, 0.f);
}

// ---------------------------------------------------------------------------
// Kernel 3: output projection, fp16 mma, split-K x4, cp.async double buffer.
// ---------------------------------------------------------------------------
#define OA_PITCH 144
#define OB_PITCH 272
#define OA_SZ (64 * OA_PITCH)
#define OB_SZ (64 * OB_PITCH)

__global__ __launch_bounds__(256, 1) void out_kernel(float* __restrict__ out) {
    __shared__ __align__(16) char smem[2 * OA_SZ + 2 * OB_SZ];
    uint32_t sbase = (uint32_t)__cvta_generic_to_shared(smem);
    uint32_t aoff[2] = { 0, OA_SZ };
    uint32_t boff[2] = { 2 * OA_SZ, 2 * OA_SZ + OB_SZ };

    int row0 = blockIdx.y * 64;
    int kz0 = blockIdx.z * (NINNER / 4);
    int tid = threadIdx.x;
    int wid = tid >> 5, lane = tid & 31;
    int lg = lane >> 2, lc = lane & 3;

    int b = row0 >> 11;
    int s_base = row0 & (NS - 1);

    auto stage = [&](int c, int bi) {
        int kk = kz0 + c * 64;
        int h = kk >> 7, d0 = kk & 127;
        const char* asrc = (const char*)&g_Oh[((size_t)(b * NH + h) * NS + s_base) * ND + d0];
        #pragma unroll
        for (int j = 0; j < 2; j++) {
            int idx = tid + j * 256;
            int r = idx >> 3, cc = (idx & 7) << 4;
            cp16(sbase + aoff[bi] + r * OA_PITCH + cc, asrc + (size_t)r * 256 + cc);
        }
        const char* bsrc = (const char*)&g_Woh[(size_t)kk * NE];
        #pragma unroll
        for (int j = 0; j < 4; j++) {
            int idx = tid + j * 256;
            int r = idx >> 4, cc = (idx & 15) << 4;
            cp16(sbase + boff[bi] + r * OB_PITCH + cc, bsrc + (size_t)r * 256 + cc);
        }
        cp_commit();
    };

    stage(0, 0);

    uint32_t laneA = ((lane & 7) + ((lane >> 3) & 1) * 8) * OA_PITCH + ((lane >> 4) & 1) * 16;
    uint32_t laneB = ((lane & 7) + ((lane >> 3) & 1) * 8) * OB_PITCH + ((lane >> 4) & 1) * 16;

    float acc[8][4] = {};

    for (int c = 0; c < 8; c++) {
        cp_wait<0>();
        __syncthreads();
        int bi = c & 1;
        if (c + 1 < 8) stage(c + 1, 1 - bi);

        uint32_t abase = sbase + aoff[bi] + (wid >> 1) * 16 * OA_PITCH + laneA;
        uint32_t bbase = sbase + boff[bi] + (wid & 1) * 128 + laneB;

        #pragma unroll
        for (int kg = 0; kg < 4; kg++) {
            uint32_t a[4];
            ldsm_x4(a, abase + kg * 32);
            #pragma unroll
            for (int nbp = 0; nbp < 4; nbp++) {
                uint32_t br[4];
                ldsm_x4t(br, bbase + kg * (16 * OB_PITCH) + nbp * 32);
                mma16(acc[2 * nbp],     a[0], a[1], a[2], a[3], br[0], br[1]);
                mma16(acc[2 * nbp + 1], a[0], a[1], a[2], a[3], br[2], br[3]);
            }
        }
        __syncthreads();
    }

    int r0 = row0 + (wid >> 1) * 16 + lg;
    int r1 = r0 + 8;
    int colb = (wid & 1) * 64;
    #pragma unroll
    for (int nb = 0; nb < 8; nb++) {
        int cc = colb + (nb >> 1) * 16 + (nb & 1) * 8 + 2 * lc;
        atomicAdd(&out[(size_t)r0 * NE + cc],     acc[nb][0]);
        atomicAdd(&out[(size_t)r0 * NE + cc + 1], acc[nb][1]);
        atomicAdd(&out[(size_t)r1 * NE + cc],     acc[nb][2]);
        atomicAdd(&out[(size_t)r1 * NE + cc + 1], acc[nb][3]);
    }
}

// ---------------------------------------------------------------------------
extern "C" void kernel_launch(void* const* d_in, const int* in_sizes, int n_in,
                              void* d_out, int out_size) {
    const float* q  = (const float*)d_in[0];
    const float* Wq = (const float*)d_in[1];
    const float* Wk = (const float*)d_in[2];
    const float* Wv = (const float*)d_in[3];
    const float* Wo = (const float*)d_in[4];
    float* out = (float*)d_out;

    cudaFuncSetAttribute(proj_kernel, cudaFuncAttributeMaxDynamicSharedMemorySize, PROJ_SMEM);
    cudaFuncSetAttribute(attn_kernel, cudaFuncAttributeMaxDynamicSharedMemorySize, ATTN_SMEM);

    rope_table_kernel<<<(NS * HALF + 255) / 256, 256>>>();

    dim3 gw(NE * NINNER / 4 / 256, 1, 4);
    wconv_kernel<<<gw, 256>>>(Wq, Wk, Wv, Wo);
    qsplit_kernel<<<NROWS * NE / 4 / 256, 256>>>(q);

    dim3 g1(NINNER / 128, NROWS / 128, 3);
    proj_kernel<<<g1, 256, PROJ_SMEM>>>();

    dim3 g2(NS / 128, NH, NB);
    attn_kernel<<<g2, 256, ATTN_SMEM>>>();

    zero_kernel<<<(NROWS * NE / 4 + 255) / 256, 256>>>(out, NROWS * NE);

    dim3 g3(1, NROWS / 64, 4);
    out_kernel<<<g3, 256>>>(out);
}

// round 17
// speedup vs baseline: 1.1152x; 1.1152x over previous
#include <cuda_runtime.h>
#include <cuda_fp16.h>
#include <math.h>
#include <stdint.h>

#define NB 2
#define NS 2048
#define NE 128
#define NH 16
#define ND 128
#define NINNER 2048
#define NROWS 4096
#define HALF 64

// Scratch
__device__ __half g_Qh[NB*NH*NS*ND];
__device__ __half g_Kh[NB*NH*NS*ND];
__device__ __half g_Vh[NB*NH*NS*ND];
__device__ __half g_Oh[NB*NH*NS*ND];
__device__ __half g_Woh[NINNER*NE];
__device__ __half g_Wqh[NE*NINNER];
__device__ __half g_Wkh[NE*NINNER];
__device__ __half g_Wvh[NE*NINNER];
__device__ __half g_qhi[NROWS*NE];
__device__ __half g_qlo[NROWS*NE];
__device__ float2 g_rope[NS*HALF];

// ---------------------------------------------------------------------------
__global__ void rope_table_kernel() {
    int idx = blockIdx.x * 256 + threadIdx.x;
    if (idx >= NS * HALF) return;
    int s = idx / HALF, p = idx % HALF;
    double inv = exp(-(double)p * (log(10000.0) / 64.0));
    double a = (double)s * inv;
    g_rope[idx] = make_float2((float)cos(a), (float)sin(a));
}

// ---------------------------------------------------------------------------
// helpers
// ---------------------------------------------------------------------------
__device__ __forceinline__ void mma16(float* c, uint32_t a0, uint32_t a1,
                                      uint32_t a2, uint32_t a3,
                                      uint32_t b0, uint32_t b1) {
    asm("mma.sync.aligned.m16n8k16.row.col.f32.f16.f16.f32 "
        "{%0,%1,%2,%3},{%4,%5,%6,%7},{%8,%9},{%0,%1,%2,%3};"
        : "+f"(c[0]), "+f"(c[1]), "+f"(c[2]), "+f"(c[3])
        : "r"(a0), "r"(a1), "r"(a2), "r"(a3), "r"(b0), "r"(b1));
}
__device__ __forceinline__ void ldsm_x4(uint32_t* r, uint32_t addr) {
    asm volatile("ldmatrix.sync.aligned.m8n8.x4.shared.b16 {%0,%1,%2,%3}, [%4];"
        : "=r"(r[0]), "=r"(r[1]), "=r"(r[2]), "=r"(r[3]) : "r"(addr));
}
__device__ __forceinline__ void ldsm_x4t(uint32_t* r, uint32_t addr) {
    asm volatile("ldmatrix.sync.aligned.m8n8.x4.trans.shared.b16 {%0,%1,%2,%3}, [%4];"
        : "=r"(r[0]), "=r"(r[1]), "=r"(r[2]), "=r"(r[3]) : "r"(addr));
}
__device__ __forceinline__ float ex2(float x) {
    float y;
    asm("ex2.approx.f32 %0, %1;" : "=f"(y) : "f"(x));
    return y;
}
__device__ __forceinline__ uint32_t h2ex2(uint32_t x) {
    uint32_t y;
    asm("ex2.approx.f16x2 %0, %1;" : "=r"(y) : "r"(x));
    return y;
}
__device__ __forceinline__ uint32_t pack2(float a, float b) {
    __half2 h = __floats2half2_rn(a, b);
    return *(uint32_t*)&h;
}
__device__ __forceinline__ void cp16(uint32_t dst, const void* src) {
    asm volatile("cp.async.cg.shared.global [%0], [%1], 16;"
                 :: "r"(dst), "l"(src));
}
__device__ __forceinline__ void cp_commit() {
    asm volatile("cp.async.commit_group;");
}
template <int N>
__device__ __forceinline__ void cp_wait() {
    asm volatile("cp.async.wait_group %0;" :: "n"(N));
}

// ---------------------------------------------------------------------------
// Kernel 0b: convert weight matrices to half
// ---------------------------------------------------------------------------
__global__ void wconv_kernel(const float* __restrict__ Wq, const float* __restrict__ Wk,
                             const float* __restrict__ Wv, const float* __restrict__ Wo) {
    int z = blockIdx.z;
    const float* src = (z == 0) ? Wq : (z == 1) ? Wk : (z == 2) ? Wv : Wo;
    __half* dst = (z == 0) ? g_Wqh : (z == 1) ? g_Wkh : (z == 2) ? g_Wvh : g_Woh;
    int i = blockIdx.x * 256 + threadIdx.x;
    float4 v = *(const float4*)&src[(size_t)i * 4];
    *(uint2*)&dst[(size_t)i * 4] = make_uint2(pack2(v.x, v.y), pack2(v.z, v.w));
}

// ---------------------------------------------------------------------------
// Kernel 0c: split activations q into f16 hi + f16 residual lo
// ---------------------------------------------------------------------------
__global__ void qsplit_kernel(const float* __restrict__ q) {
    int i = blockIdx.x * 256 + threadIdx.x;
    float4 v = *(const float4*)&q[(size_t)i * 4];
    __half hx = __float2half_rn(v.x), hy = __float2half_rn(v.y);
    __half hz = __float2half_rn(v.z), hw = __float2half_rn(v.w);
    __half2 h0 = __halves2half2(hx, hy), h1 = __halves2half2(hz, hw);
    *(uint2*)&g_qhi[(size_t)i * 4] = make_uint2(*(uint32_t*)&h0, *(uint32_t*)&h1);
    float lx = v.x - __half2float(hx), ly = v.y - __half2float(hy);
    float lz = v.z - __half2float(hz), lw = v.w - __half2float(hw);
    *(uint2*)&g_qlo[(size_t)i * 4] = make_uint2(pack2(lx, ly), pack2(lz, lw));
}

// ---------------------------------------------------------------------------
// Kernel 1: fused QKV projection, fp16 mma with split-A compensation + RoPE.
// ---------------------------------------------------------------------------
#define PPITCH 272
#define PA_SZ (128 * PPITCH)
#define PROJ_SMEM (3 * PA_SZ)

__global__ __launch_bounds__(256, 1) void proj_kernel() {
    extern __shared__ char psm[];
    uint32_t sbase = (uint32_t)__cvta_generic_to_shared(psm);
    uint32_t ahi_off = 0, alo_off = PA_SZ, b_off = 2 * PA_SZ;

    int z = blockIdx.z;
    const __half* W = (z == 0) ? g_Wqh : (z == 1) ? g_Wkh : g_Wvh;
    __half* dst = (z == 0) ? g_Qh : (z == 1) ? g_Kh : g_Vh;

    int h = blockIdx.x;
    int row0 = blockIdx.y * 128;
    int col0 = h * 128;
    int tid = threadIdx.x;
    int wid = tid >> 5, lane = tid & 31;
    int lg = lane >> 2, lc = lane & 3;

    #pragma unroll
    for (int j = 0; j < 8; j++) {
        int idx = tid + j * 256;
        int r = idx >> 4, c = (idx & 15) << 4;
        cp16(sbase + ahi_off + r * PPITCH + c,
             (const char*)&g_qhi[(size_t)(row0 + r) * NE] + c);
        cp16(sbase + alo_off + r * PPITCH + c,
             (const char*)&g_qlo[(size_t)(row0 + r) * NE] + c);
        cp16(sbase + b_off + r * PPITCH + c,
             (const char*)&W[(size_t)r * NINNER + col0] + c);
    }
    cp_commit();
    cp_wait<0>();
    __syncthreads();

    uint32_t laneQ = ((lane & 7) + ((lane >> 3) & 1) * 8) * PPITCH + ((lane >> 4) & 1) * 16;

    uint32_t ahi[8][4], alo[8][4];
    {
        uint32_t abase_h = sbase + ahi_off + wid * 16 * PPITCH + laneQ;
        uint32_t abase_l = sbase + alo_off + wid * 16 * PPITCH + laneQ;
        #pragma unroll
        for (int kg = 0; kg < 8; kg++) {
            ldsm_x4(ahi[kg], abase_h + kg * 32);
            ldsm_x4(alo[kg], abase_l + kg * 32);
        }
    }

    float acc[16][4] = {};
    uint32_t bbase = sbase + b_off + laneQ;
    #pragma unroll
    for (int kg = 0; kg < 8; kg++) {
        #pragma unroll
        for (int nbp = 0; nbp < 8; nbp++) {
            uint32_t br[4];
            ldsm_x4t(br, bbase + kg * (16 * PPITCH) + nbp * 32);
            mma16(acc[2 * nbp],     ahi[kg][0], ahi[kg][1], ahi[kg][2], ahi[kg][3], br[0], br[1]);
            mma16(acc[2 * nbp],     alo[kg][0], alo[kg][1], alo[kg][2], alo[kg][3], br[0], br[1]);
            mma16(acc[2 * nbp + 1], ahi[kg][0], ahi[kg][1], ahi[kg][2], ahi[kg][3], br[2], br[3]);
            mma16(acc[2 * nbp + 1], alo[kg][0], alo[kg][1], alo[kg][2], alo[kg][3], br[2], br[3]);
        }
    }

    const float qscale = 0.08838834764831845f * 1.4426950408889634f;
    float oscale = (z == 0) ? qscale : 1.0f;
    bool do_rope = (z < 2);

    int row_a = row0 + wid * 16 + lg;
    int b = row_a >> 11;
    int s0 = row_a & (NS - 1);
    int s1 = s0 + 8;
    __half* d0p = &dst[((size_t)(b * NH + h) * NS + s0) * ND];
    __half* d1p = &dst[((size_t)(b * NH + h) * NS + s1) * ND];

    #pragma unroll
    for (int nb = 0; nb < 16; nb++) {
        int dcol = nb * 8 + 2 * lc;
        int p = nb * 4 + lc;
        float c0 = acc[nb][0], c1 = acc[nb][1];
        float c2 = acc[nb][2], c3 = acc[nb][3];
        if (do_rope) {
            float2 csa = g_rope[s0 * HALF + p];
            float2 csb = g_rope[s1 * HALF + p];
            float r0 = c0 * csa.x - c1 * csa.y;
            float r1 = c1 * csa.x + c0 * csa.y;
            float r2 = c2 * csb.x - c3 * csb.y;
            float r3 = c3 * csb.x + c2 * csb.y;
            c0 = r0; c1 = r1; c2 = r2; c3 = r3;
        }
        *(uint32_t*)&d0p[dcol] = pack2(c0 * oscale, c1 * oscale);
        *(uint32_t*)&d1p[dcol] = pack2(c2 * oscale, c3 * oscale);
    }
}

// ---------------------------------------------------------------------------
// Kernel 2: causal flash attention, fp16 mma, cp.async pipeline.
// CTA = 128 threads (4 warps), Q tile 64 rows -> ~25.6K regs/CTA so
// TWO CTAs co-reside per SM; their softmax/barrier stalls interleave.
// smem: K double buf + V double buf + Q stage = 5*17408 = 87040 B.
// ---------------------------------------------------------------------------
#define PITCHB 272
#define KS_SZ  (64 * PITCHB)
#define KS_OFF 0
#define VS_OFF (2 * KS_SZ)
#define QST_OFF (4 * KS_SZ)
#define ATTN_SMEM (QST_OFF + 64 * PITCHB)

__global__ __launch_bounds__(128, 2) void attn_kernel() {
    extern __shared__ char smem[];
    uint32_t sbase = (uint32_t)__cvta_generic_to_shared(smem);

    int qt = gridDim.x - 1 - blockIdx.x;   // heavy tiles first
    int h = blockIdx.y, b = blockIdx.z;
    const __half* Qg = &g_Qh[((size_t)(b * NH + h) * NS + qt * 64) * ND];
    const __half* Kg = &g_Kh[(size_t)(b * NH + h) * NS * ND];
    const __half* Vg = &g_Vh[(size_t)(b * NH + h) * NS * ND];

    int tid = threadIdx.x;
    int wid = tid >> 5, lane = tid & 31;
    int lg = lane >> 2, lc = lane & 3;

    int nkt = qt + 1;
    uint32_t ones_b = (lg == 0) ? 0x3C003C00u : 0u;   // B frag: col n=0 ones

    // prologue: commit K0,V0; stage Q
    {
        const char* sk = (const char*)Kg;
        const char* sv = (const char*)Vg;
        #pragma unroll
        for (int j = 0; j < 8; j++) {
            int idx = tid + j * 128;
            int r = idx >> 4, c = (idx & 15) << 4;
            cp16(sbase + KS_OFF + r * PITCHB + c, sk + r * 256 + c);
            cp16(sbase + VS_OFF + r * PITCHB + c, sv + r * 256 + c);
        }
        cp_commit();
    }
    #pragma unroll
    for (int j = 0; j < 8; j++) {
        int idx = tid + j * 128;
        int r = idx >> 4, c = (idx & 15) << 4;
        *(uint4*)(smem + QST_OFF + r * PITCHB + c) =
            *(const uint4*)((const char*)Qg + r * 256 + c);
    }
    __syncthreads();

    uint32_t laneQ = ((lane & 7) + ((lane >> 3) & 1) * 8) * PITCHB + ((lane >> 4) & 1) * 16;
    uint32_t laneK = ((lane & 7) + ((lane >> 4) & 1) * 8) * PITCHB + ((lane >> 3) & 1) * 16;
    uint32_t laneV = laneQ;

    uint32_t qa[8][4];
    {
        uint32_t qaddr = sbase + QST_OFF + wid * 16 * PITCHB + laneQ;
        #pragma unroll
        for (int kg = 0; kg < 8; kg++) ldsm_x4(qa[kg], qaddr + kg * 32);
    }

    float oacc[16][4] = {};
    float lrow[4] = {};
    float m0 = -1e30f, m1 = -1e30f;
    int row_g0 = qt * 64 + wid * 16 + lg;
    int row_g1 = row_g0 + 8;

    for (int kt = 0; kt < nkt; kt++) {
        cp_wait<0>();
        __syncthreads();

        int buf = kt & 1;
        if (kt + 1 < nkt) {
            const char* sk = (const char*)(Kg + (size_t)(kt + 1) * 64 * ND);
            const char* sv = (const char*)(Vg + (size_t)(kt + 1) * 64 * ND);
            uint32_t kd = sbase + KS_OFF + (1 - buf) * KS_SZ;
            uint32_t vd = sbase + VS_OFF + (1 - buf) * KS_SZ;
            #pragma unroll
            for (int j = 0; j < 8; j++) {
                int idx = tid + j * 128;
                int r = idx >> 4, c = (idx & 15) << 4;
                cp16(kd + r * PITCHB + c, sk + r * 256 + c);
                cp16(vd + r * PITCHB + c, sv + r * 256 + c);
            }
            cp_commit();
        }

        // ---- S = Q @ K^T ----
        uint32_t kbase = sbase + KS_OFF + buf * KS_SZ + laneK;
        float sacc[8][4] = {};
        #pragma unroll
        for (int kg = 0; kg < 8; kg++) {
            #pragma unroll
            for (int nbp = 0; nbp < 4; nbp++) {
                uint32_t br[4];
                ldsm_x4(br, kbase + nbp * (16 * PITCHB) + kg * 32);
                mma16(sacc[2 * nbp],     qa[kg][0], qa[kg][1], qa[kg][2], qa[kg][3], br[0], br[1]);
                mma16(sacc[2 * nbp + 1], qa[kg][0], qa[kg][1], qa[kg][2], qa[kg][3], br[2], br[3]);
            }
        }

        // ---- causal mask (diagonal tile only) ----
        if (kt == qt) {
            #pragma unroll
            for (int nb = 0; nb < 8; nb++) {
                int col_g = kt * 64 + nb * 8 + 2 * lc;
                if (col_g     > row_g0) sacc[nb][0] = -1e30f;
                if (col_g + 1 > row_g0) sacc[nb][1] = -1e30f;
                if (col_g     > row_g1) sacc[nb][2] = -1e30f;
                if (col_g + 1 > row_g1) sacc[nb][3] = -1e30f;
            }
        }

        // ---- online softmax (log2 domain) ----
        float mt0 = -1e30f, mt1 = -1e30f;
        #pragma unroll
        for (int nb = 0; nb < 8; nb++) {
            mt0 = fmaxf(mt0, fmaxf(sacc[nb][0], sacc[nb][1]));
            mt1 = fmaxf(mt1, fmaxf(sacc[nb][2], sacc[nb][3]));
        }
        mt0 = fmaxf(mt0, __shfl_xor_sync(0xFFFFFFFFu, mt0, 1));
        mt0 = fmaxf(mt0, __shfl_xor_sync(0xFFFFFFFFu, mt0, 2));
        mt1 = fmaxf(mt1, __shfl_xor_sync(0xFFFFFFFFu, mt1, 1));
        mt1 = fmaxf(mt1, __shfl_xor_sync(0xFFFFFFFFu, mt1, 2));
        float mn0 = fmaxf(m0, mt0), mn1 = fmaxf(m1, mt1);
        float al0 = ex2(m0 - mn0), al1 = ex2(m1 - mn1);
        m0 = mn0; m1 = mn1;

        // p = 2^(s-m) in f16x2
        uint32_t ph[8][2];
        #pragma unroll
        for (int nb = 0; nb < 8; nb++) {
            ph[nb][0] = h2ex2(pack2(sacc[nb][0] - mn0, sacc[nb][1] - mn0));
            ph[nb][1] = h2ex2(pack2(sacc[nb][2] - mn1, sacc[nb][3] - mn1));
        }

        // rescale O and l
        #pragma unroll
        for (int nb = 0; nb < 16; nb++) {
            oacc[nb][0] *= al0; oacc[nb][1] *= al0;
            oacc[nb][2] *= al1; oacc[nb][3] *= al1;
        }
        lrow[0] *= al0; lrow[1] *= al0; lrow[2] *= al1; lrow[3] *= al1;

        // l += P @ ones
        #pragma unroll
        for (int kg = 0; kg < 4; kg++)
            mma16(lrow, ph[2 * kg][0], ph[2 * kg][1],
                  ph[2 * kg + 1][0], ph[2 * kg + 1][1], ones_b, ones_b);

        // ---- O += P @ V ----
        uint32_t vbase = sbase + VS_OFF + buf * KS_SZ + laneV;
        #pragma unroll
        for (int kg = 0; kg < 4; kg++) {
            uint32_t a0 = ph[2 * kg][0], a1 = ph[2 * kg][1];
            uint32_t a2 = ph[2 * kg + 1][0], a3 = ph[2 * kg + 1][1];
            #pragma unroll
            for (int nbp = 0; nbp < 8; nbp++) {
                uint32_t br[4];
                ldsm_x4t(br, vbase + kg * (16 * PITCHB) + nbp * 32);
                mma16(oacc[2 * nbp],     a0, a1, a2, a3, br[0], br[1]);
                mma16(oacc[2 * nbp + 1], a0, a1, a2, a3, br[2], br[3]);
            }
        }
    }

    // ---- epilogue ----
    float lt0 = __shfl_sync(0xFFFFFFFFu, lrow[0], lane & 28);
    float lt1 = __shfl_sync(0xFFFFFFFFu, lrow[2], lane & 28);
    float inv0 = 1.0f / lt0, inv1 = 1.0f / lt1;
    __half* Og = &g_Oh[((size_t)(b * NH + h) * NS + qt * 64) * ND];
    #pragma unroll
    for (int nb = 0; nb < 16; nb++) {
        int c = nb * 8 + 2 * lc;
        *(uint32_t*)&Og[(size_t)(wid * 16 + lg) * ND + c] =
            pack2(oacc[nb][0] * inv0, oacc[nb][1] * inv0);
        *(uint32_t*)&Og[(size_t)(wid * 16 + lg + 8) * ND + c] =
            pack2(oacc[nb][2] * inv1, oacc[nb][3] * inv1);
    }
}

// ---------------------------------------------------------------------------
__global__ void zero_kernel(float* __restrict__ out, int n) {
    int i = blockIdx.x * 256 + threadIdx.x;
    if (i * 4 < n) *(float4*)&out[i * 4] = make_float4(0.f, 0.f, 0.f, 0.f);
}

// ---------------------------------------------------------------------------
// Kernel 3: output projection, fp16 mma, split-K x4, cp.async double buffer.
// ---------------------------------------------------------------------------
#define OA_PITCH 144
#define OB_PITCH 272
#define OA_SZ (64 * OA_PITCH)
#define OB_SZ (64 * OB_PITCH)

__global__ __launch_bounds__(256, 1) void out_kernel(float* __restrict__ out) {
    __shared__ __align__(16) char smem[2 * OA_SZ + 2 * OB_SZ];
    uint32_t sbase = (uint32_t)__cvta_generic_to_shared(smem);
    uint32_t aoff[2] = { 0, OA_SZ };
    uint32_t boff[2] = { 2 * OA_SZ, 2 * OA_SZ + OB_SZ };

    int row0 = blockIdx.y * 64;
    int kz0 = blockIdx.z * (NINNER / 4);
    int tid = threadIdx.x;
    int wid = tid >> 5, lane = tid & 31;
    int lg = lane >> 2, lc = lane & 3;

    int b = row0 >> 11;
    int s_base = row0 & (NS - 1);

    auto stage = [&](int c, int bi) {
        int kk = kz0 + c * 64;
        int h = kk >> 7, d0 = kk & 127;
        const char* asrc = (const char*)&g_Oh[((size_t)(b * NH + h) * NS + s_base) * ND + d0];
        #pragma unroll
        for (int j = 0; j < 2; j++) {
            int idx = tid + j * 256;
            int r = idx >> 3, cc = (idx & 7) << 4;
            cp16(sbase + aoff[bi] + r * OA_PITCH + cc, asrc + (size_t)r * 256 + cc);
        }
        const char* bsrc = (const char*)&g_Woh[(size_t)kk * NE];
        #pragma unroll
        for (int j = 0; j < 4; j++) {
            int idx = tid + j * 256;
            int r = idx >> 4, cc = (idx & 15) << 4;
            cp16(sbase + boff[bi] + r * OB_PITCH + cc, bsrc + (size_t)r * 256 + cc);
        }
        cp_commit();
    };

    stage(0, 0);

    uint32_t laneA = ((lane & 7) + ((lane >> 3) & 1) * 8) * OA_PITCH + ((lane >> 4) & 1) * 16;
    uint32_t laneB = ((lane & 7) + ((lane >> 3) & 1) * 8) * OB_PITCH + ((lane >> 4) & 1) * 16;

    float acc[8][4] = {};

    for (int c = 0; c < 8; c++) {
        cp_wait<0>();
        __syncthreads();
        int bi = c & 1;
        if (c + 1 < 8) stage(c + 1, 1 - bi);

        uint32_t abase = sbase + aoff[bi] + (wid >> 1) * 16 * OA_PITCH + laneA;
        uint32_t bbase = sbase + boff[bi] + (wid & 1) * 128 + laneB;

        #pragma unroll
        for (int kg = 0; kg < 4; kg++) {
            uint32_t a[4];
            ldsm_x4(a, abase + kg * 32);
            #pragma unroll
            for (int nbp = 0; nbp < 4; nbp++) {
                uint32_t br[4];
                ldsm_x4t(br, bbase + kg * (16 * OB_PITCH) + nbp * 32);
                mma16(acc[2 * nbp],     a[0], a[1], a[2], a[3], br[0], br[1]);
                mma16(acc[2 * nbp + 1], a[0], a[1], a[2], a[3], br[2], br[3]);
            }
        }
        __syncthreads();
    }

    int r0 = row0 + (wid >> 1) * 16 + lg;
    int r1 = r0 + 8;
    int colb = (wid & 1) * 64;
    #pragma unroll
    for (int nb = 0; nb < 8; nb++) {
        int cc = colb + (nb >> 1) * 16 + (nb & 1) * 8 + 2 * lc;
        atomicAdd(&out[(size_t)r0 * NE + cc],     acc[nb][0]);
        atomicAdd(&out[(size_t)r0 * NE + cc + 1], acc[nb][1]);
        atomicAdd(&out[(size_t)r1 * NE + cc],     acc[nb][2]);
        atomicAdd(&out[(size_t)r1 * NE + cc + 1], acc[nb][3]);
    }
}

// ---------------------------------------------------------------------------
extern "C" void kernel_launch(void* const* d_in, const int* in_sizes, int n_in,
                              void* d_out, int out_size) {
    const float* q  = (const float*)d_in[0];
    const float* Wq = (const float*)d_in[1];
    const float* Wk = (const float*)d_in[2];
    const float* Wv = (const float*)d_in[3];
    const float* Wo = (const float*)d_in[4];
    float* out = (float*)d_out;

    cudaFuncSetAttribute(proj_kernel, cudaFuncAttributeMaxDynamicSharedMemorySize, PROJ_SMEM);
    cudaFuncSetAttribute(attn_kernel, cudaFuncAttributeMaxDynamicSharedMemorySize, ATTN_SMEM);

    rope_table_kernel<<<(NS * HALF + 255) / 256, 256>>>();

    dim3 gw(NE * NINNER / 4 / 256, 1, 4);
    wconv_kernel<<<gw, 256>>>(Wq, Wk, Wv, Wo);
    qsplit_kernel<<<NROWS * NE / 4 / 256, 256>>>(q);

    dim3 g1(NINNER / 128, NROWS / 128, 3);
    proj_kernel<<<g1, 256, PROJ_SMEM>>>();

    dim3 g2(NS / 64, NH, NB);
    attn_kernel<<<g2, 128, ATTN_SMEM>>>();

    zero_kernel<<<(NROWS * NE / 4 + 255) / 256, 256>>>(out, NROWS * NE);

    dim3 g3(1, NROWS / 64, 4);
    out_kernel<<<g3, 256>>>(out);
}